// round 1
// baseline (speedup 1.0000x reference)
#include <cuda_runtime.h>
#include <cuda_bf16.h>

#define BWIN 4096
#define NTOK 49
#define DIMV 256
#define NH   8
#define HD   32
#define QKVN 768
#define QSCALE 0.17677669529663687f   // 32^-0.5

// ---- scratch (device globals; no allocation allowed) ----
__device__ float g_Q[(size_t)BWIN * NH * NTOK * HD];
__device__ float g_K[(size_t)BWIN * NH * NTOK * HD];
__device__ float g_V[(size_t)BWIN * NH * NTOK * HD];
__device__ float g_ctx[(size_t)BWIN * NTOK * DIMV];

// ============================================================
// Generic fp32 SGEMM: C[M x LDB] = A[M x 256] * B[256 x LDB] + bias
// BM=128, BN=64, BK=16, 256 threads, thread tile 8x4.
// EPI==0: scatter into g_Q/g_K/g_V (qkv epilogue, Q pre-scaled)
// EPI==1: A is g_ctx, write dense to Cout with bias
// ============================================================
template<int LDB, int EPI>
__global__ __launch_bounds__(256)
void sgemm_kernel(const float* __restrict__ A, const float* __restrict__ Bw,
                  const float* __restrict__ bias, float* __restrict__ Cout)
{
    constexpr int BM = 128, BN = 64, BK = 16;
    __shared__ float As[BK][BM];
    __shared__ float Bs[BK][BN];

    const int tid = threadIdx.x;
    const int bm = blockIdx.y, bn = blockIdx.x;
    const int ty = tid >> 4, tx = tid & 15;

    const float* Abase = (EPI == 1) ? (const float*)g_ctx : A;
    const float* Ab = Abase + (size_t)bm * BM * DIMV;
    const float* Bb = Bw + bn * BN;

    float acc[8][4];
#pragma unroll
    for (int i = 0; i < 8; i++)
#pragma unroll
        for (int j = 0; j < 4; j++) acc[i][j] = 0.f;

    for (int k0 = 0; k0 < DIMV; k0 += BK) {
        // load A tile (128 rows x 16 cols), transpose into As[k][m]
#pragma unroll
        for (int i = 0; i < 2; i++) {
            int s = tid + i * 256;          // 512 float4 slots
            int r = s >> 2;
            int c = (s & 3) << 2;
            float4 v = *(const float4*)(Ab + (size_t)r * DIMV + k0 + c);
            As[c + 0][r] = v.x;
            As[c + 1][r] = v.y;
            As[c + 2][r] = v.z;
            As[c + 3][r] = v.w;
        }
        // load B tile (16 rows x 64 cols)
        {
            int r = tid >> 4;
            int c = (tid & 15) << 2;
            float4 v = *(const float4*)(Bb + (size_t)(k0 + r) * LDB + c);
            *(float4*)(&Bs[r][c]) = v;
        }
        __syncthreads();

#pragma unroll
        for (int k = 0; k < BK; k++) {
            float a[8], b[4];
            *(float4*)(a)     = *(const float4*)(&As[k][ty * 8]);
            *(float4*)(a + 4) = *(const float4*)(&As[k][ty * 8 + 4]);
            *(float4*)(b)     = *(const float4*)(&Bs[k][tx * 4]);
#pragma unroll
            for (int i = 0; i < 8; i++)
#pragma unroll
                for (int j = 0; j < 4; j++)
                    acc[i][j] = fmaf(a[i], b[j], acc[i][j]);
        }
        __syncthreads();
    }

    const int row0 = bm * BM + ty * 8;
    const int col0 = bn * BN + tx * 4;

    if (EPI == 0) {
        // qkv scatter: col -> (h, d, s) = (col/96, (col/3)%32, col%3)
#pragma unroll
        for (int i = 0; i < 8; i++) {
            int row = row0 + i;
            int b = row / NTOK;
            int n = row - b * NTOK;
#pragma unroll
            for (int j = 0; j < 4; j++) {
                int col = col0 + j;
                float v = acc[i][j] + bias[col];
                int s = col % 3;
                int d = (col / 3) & 31;
                int h = col / 96;
                size_t addr = (((size_t)(b * NH + h)) * NTOK + n) * HD + d;
                if (s == 0)      g_Q[addr] = v * QSCALE;
                else if (s == 1) g_K[addr] = v;
                else             g_V[addr] = v;
            }
        }
    } else {
#pragma unroll
        for (int i = 0; i < 8; i++) {
            float4 v;
            v.x = acc[i][0] + bias[col0 + 0];
            v.y = acc[i][1] + bias[col0 + 1];
            v.z = acc[i][2] + bias[col0 + 2];
            v.w = acc[i][3] + bias[col0 + 3];
            *(float4*)(Cout + (size_t)(row0 + i) * LDB + col0) = v;
        }
    }
}

// ============================================================
// Attention: one CTA per (window b, head h). 196 threads.
// Q row cached in registers (4 threads per query row).
// ============================================================
__global__ __launch_bounds__(196)
void attn_kernel(const int* __restrict__ mask, const float* __restrict__ bias_table)
{
    __shared__ float sK[NTOK * HD];
    __shared__ float sV[NTOK * HD];
    __shared__ float sA[NTOK * NTOK];
    __shared__ float sBias[169];

    const int bh = blockIdx.x;
    const int b = bh >> 3, h = bh & 7;
    const int tid = threadIdx.x;

    const float* Qb = g_Q + (size_t)bh * NTOK * HD;
    const float* Kb = g_K + (size_t)bh * NTOK * HD;
    const float* Vb = g_V + (size_t)bh * NTOK * HD;

    for (int i = tid; i < NTOK * HD / 4; i += blockDim.x) {
        ((float4*)sK)[i] = ((const float4*)Kb)[i];
        ((float4*)sV)[i] = ((const float4*)Vb)[i];
    }
    for (int i = tid; i < 169; i += blockDim.x)
        sBias[i] = bias_table[i * NH + h];
    __syncthreads();

    // ---- phase 1: S = Q K^T + bias + maskterm ----
    {
        const int q = tid >> 2;   // 0..48 (196 = 49*4 threads)
        float qr[HD];
#pragma unroll
        for (int d4 = 0; d4 < HD / 4; d4++) {
            float4 v = ((const float4*)(Qb + q * HD))[d4];
            qr[d4 * 4 + 0] = v.x; qr[d4 * 4 + 1] = v.y;
            qr[d4 * 4 + 2] = v.z; qr[d4 * 4 + 3] = v.w;
        }
        const int qi = q / 7, qj = q - qi * 7;
        const int* mrow = mask + (size_t)b * NTOK * NTOK + q * NTOK;
        for (int k = (tid & 3); k < NTOK; k += 4) {
            float s = 0.f;
#pragma unroll
            for (int d4 = 0; d4 < HD / 4; d4++) {
                float4 kv = ((const float4*)(sK + k * HD))[d4];
                s = fmaf(qr[d4 * 4 + 0], kv.x, s);
                s = fmaf(qr[d4 * 4 + 1], kv.y, s);
                s = fmaf(qr[d4 * 4 + 2], kv.z, s);
                s = fmaf(qr[d4 * 4 + 3], kv.w, s);
            }
            int ki = k / 7, kj = k - ki * 7;
            int ridx = (qi - ki + 6) * 13 + (qj - kj + 6);
            s += sBias[ridx];
            s += (1.0f - (float)mrow[k]) * (-1e10f);
            sA[q * NTOK + k] = s;
        }
    }
    __syncthreads();

    // ---- phase 2: softmax, one thread per row ----
    if (tid < NTOK) {
        float* r = sA + tid * NTOK;
        float m = r[0];
#pragma unroll 7
        for (int k = 1; k < NTOK; k++) m = fmaxf(m, r[k]);
        float sum = 0.f;
#pragma unroll 7
        for (int k = 0; k < NTOK; k++) { float e = __expf(r[k] - m); r[k] = e; sum += e; }
        float inv = 1.0f / sum;
#pragma unroll 7
        for (int k = 0; k < NTOK; k++) r[k] *= inv;
    }
    __syncthreads();

    // ---- phase 3: O = P V, write to ctx [b, n, h*32 + d] ----
    float* ctx = g_ctx + (size_t)b * NTOK * DIMV + h * HD;
    for (int e = tid; e < NTOK * HD; e += blockDim.x) {
        int qq = e >> 5, d = e & 31;
        float s = 0.f;
        const float* ar = sA + qq * NTOK;
#pragma unroll 7
        for (int k = 0; k < NTOK; k++)
            s = fmaf(ar[k], sV[k * HD + d], s);
        ctx[(size_t)qq * DIMV + d] = s;
    }
}

// ============================================================
extern "C" void kernel_launch(void* const* d_in, const int* in_sizes, int n_in,
                              void* d_out, int out_size)
{
    const float* x       = (const float*)d_in[0];
    const int*   mask    = (const int*)d_in[1];
    const float* qkv_w   = (const float*)d_in[2];
    const float* qkv_b   = (const float*)d_in[3];
    const float* proj_w  = (const float*)d_in[4];
    const float* proj_b  = (const float*)d_in[5];
    const float* rel_tbl = (const float*)d_in[6];
    float* out = (float*)d_out;

    const int M = BWIN * NTOK;   // 200704

    dim3 g1(QKVN / 64, M / 128);
    sgemm_kernel<QKVN, 0><<<g1, 256>>>(x, qkv_w, qkv_b, nullptr);

    attn_kernel<<<BWIN * NH, 196>>>(mask, rel_tbl);

    dim3 g3(DIMV / 64, M / 128);
    sgemm_kernel<DIMV, 1><<<g3, 256>>>(nullptr, proj_w, proj_b, out);
}

// round 3
// speedup vs baseline: 1.3127x; 1.3127x over previous
#include <cuda_runtime.h>
#include <cuda_bf16.h>
#include <cstdint>

#define BWIN 4096
#define NTOK 49
#define DIMV 256
#define NH   8
#define HD   32
#define MTOT (BWIN*NTOK)              /* 200704 */
#define KCAT 768                      /* 3 x 256 (hi|lo|hi) */
#define QSCALE 0.17677669529663687f   /* 32^-0.5 */

// ================= scratch (device globals; no allocation allowed) =========
__device__ __nv_bfloat16 g_xcat[(size_t)MTOT * KCAT];   // [hi | lo | hi]
__device__ __nv_bfloat16 g_ccat[(size_t)MTOT * KCAT];   // attention out, same layout
__device__ __nv_bfloat16 g_wq[768 * KCAT];              // [n][hi | hi | lo]
__device__ __nv_bfloat16 g_wp[256 * KCAT];
__device__ float g_Q[(size_t)BWIN * NH * NTOK * HD];
__device__ float g_K[(size_t)BWIN * NH * NTOK * HD];
__device__ float g_V[(size_t)BWIN * NH * NTOK * HD];

// ======================= helpers ===========================================
__device__ __forceinline__ uint32_t smem_u32(const void* p) {
    uint32_t a;
    asm("{ .reg .u64 t; cvta.to.shared.u64 t, %1; cvt.u32.u64 %0, t; }" : "=r"(a) : "l"(p));
    return a;
}
__device__ __forceinline__ void cp16(uint32_t sdst, const void* g) {
    asm volatile("cp.async.cg.shared.global [%0], [%1], 16;" :: "r"(sdst), "l"(g));
}
#define CP_COMMIT() asm volatile("cp.async.commit_group;" ::: "memory")

__device__ __forceinline__ void ldsm_x4(uint32_t (&r)[4], uint32_t addr) {
    asm volatile("ldmatrix.sync.aligned.m8n8.x4.shared.b16 {%0,%1,%2,%3}, [%4];"
                 : "=r"(r[0]), "=r"(r[1]), "=r"(r[2]), "=r"(r[3]) : "r"(addr));
}
__device__ __forceinline__ void mma16816(float (&d)[4], const uint32_t (&a)[4],
                                         uint32_t b0, uint32_t b1) {
    asm volatile("mma.sync.aligned.m16n8k16.row.col.f32.bf16.bf16.f32 "
                 "{%0,%1,%2,%3}, {%4,%5,%6,%7}, {%8,%9}, {%0,%1,%2,%3};"
                 : "+f"(d[0]), "+f"(d[1]), "+f"(d[2]), "+f"(d[3])
                 : "r"(a[0]), "r"(a[1]), "r"(a[2]), "r"(a[3]), "r"(b0), "r"(b1));
}

// ======================= split / pack kernels ==============================
// x [MTOT,256] fp32 -> xcat [MTOT,768] bf16 blocks [hi | lo | hi]
__global__ __launch_bounds__(256) void k_split_x(const float* __restrict__ in,
                                                 __nv_bfloat16* __restrict__ cat) {
    size_t gi = ((size_t)blockIdx.x * 256 + threadIdx.x) * 4;
    size_t m = gi >> 8;
    int k = (int)(gi & 255);
    float4 v = *(const float4*)(in + gi);
    __nv_bfloat16 h0 = __float2bfloat16(v.x), h1 = __float2bfloat16(v.y);
    __nv_bfloat16 h2 = __float2bfloat16(v.z), h3 = __float2bfloat16(v.w);
    __nv_bfloat162 hA = __halves2bfloat162(h0, h1), hB = __halves2bfloat162(h2, h3);
    __nv_bfloat162 lA = __halves2bfloat162(__float2bfloat16(v.x - __bfloat162float(h0)),
                                           __float2bfloat16(v.y - __bfloat162float(h1)));
    __nv_bfloat162 lB = __halves2bfloat162(__float2bfloat16(v.z - __bfloat162float(h2)),
                                           __float2bfloat16(v.w - __bfloat162float(h3)));
    __nv_bfloat16* row = cat + m * KCAT;
    *(__nv_bfloat162*)(row + k)           = hA; *(__nv_bfloat162*)(row + k + 2)       = hB;
    *(__nv_bfloat162*)(row + 256 + k)     = lA; *(__nv_bfloat162*)(row + 256 + k + 2) = lB;
    *(__nv_bfloat162*)(row + 512 + k)     = hA; *(__nv_bfloat162*)(row + 512 + k + 2) = hB;
}

// w [256,N] fp32 -> wcat [N,768] bf16 blocks [hi | hi | lo] (k-major)
__global__ __launch_bounds__(256) void k_split_w(const float* __restrict__ w,
                                                 __nv_bfloat16* __restrict__ cat, int N) {
    int i = blockIdx.x * 256 + threadIdx.x;   // over 256*N
    int k = i / N, n = i - k * N;
    float v = w[i];
    __nv_bfloat16 h = __float2bfloat16(v);
    __nv_bfloat16 l = __float2bfloat16(v - __bfloat162float(h));
    __nv_bfloat16* row = cat + (size_t)n * KCAT;
    row[k] = h; row[256 + k] = h; row[512 + k] = l;
}

// ======================= HMMA GEMM =========================================
// C[128 x 128 tile] = A'[M,768] * B'[N,768]^T (both k-major bf16), fp32 acc.
// EPI 0: qkv scatter (+bias, Q scaled). EPI 1: dense out (+bias), pitch 256.
template<int EPI>
__global__ __launch_bounds__(256, 2) void mma_gemm(const float* __restrict__ bias,
                                                   float* __restrict__ out) {
    // smem: [stage][A|B][128 rows x 40 bf16 (32 data + 8 pad)]
    __shared__ __align__(16) __nv_bfloat16 sm[2][2][128 * 40];
    const uint32_t sb = smem_u32(sm);
    constexpr uint32_t TILEB = 128 * 40 * 2;   // 10240 bytes

    const int tid = threadIdx.x;
    const int wid = tid >> 5, lane = tid & 31;
    const int warp_m = wid & 1, warp_n = wid >> 1;

    const __nv_bfloat16* gA = (EPI ? g_ccat : g_xcat) + (size_t)blockIdx.y * 128 * KCAT;
    const __nv_bfloat16* gB = (EPI ? g_wp   : g_wq)   + (size_t)blockIdx.x * 128 * KCAT;

    float acc[4][4][4];
#pragma unroll
    for (int a = 0; a < 4; a++)
#pragma unroll
        for (int b = 0; b < 4; b++)
#pragma unroll
            for (int c = 0; c < 4; c++) acc[a][b][c] = 0.f;

    auto load_stage = [&](int it) {
        const int k0 = it * 32;
        const uint32_t st = sb + (uint32_t)(it & 1) * (2 * TILEB);
#pragma unroll
        for (int j = 0; j < 4; j++) {
            int cid = tid + j * 256;            // 0..1023
            int half = cid >> 9;                // 0=A, 1=B
            int r = (cid >> 2) & 127;
            int c = cid & 3;
            const __nv_bfloat16* src = (half ? gB : gA) + (size_t)r * KCAT + k0 + c * 8;
            cp16(st + (uint32_t)half * TILEB + (uint32_t)(r * 80 + c * 16), src);
        }
        CP_COMMIT();
    };

    // ldmatrix lane address components
    const int a_row = (lane & 7) + 8 * ((lane >> 3) & 1);   // within m16
    const int a_kb  = ((lane >> 4) & 1) * 16;               // k-half bytes
    const int b_row = (lane & 7) + 8 * ((lane >> 4) & 1);   // within n16
    const int b_kb  = ((lane >> 3) & 1) * 16;

    load_stage(0);

#pragma unroll 1
    for (int it = 0; it < 24; ++it) {
        if (it + 1 < 24) {
            load_stage(it + 1);
            asm volatile("cp.async.wait_group 1;" ::: "memory");
        } else {
            asm volatile("cp.async.wait_group 0;" ::: "memory");
        }
        __syncthreads();

        const uint32_t sA = sb + (uint32_t)(it & 1) * (2 * TILEB);
        const uint32_t sB = sA + TILEB;
#pragma unroll
        for (int h16 = 0; h16 < 2; h16++) {
            uint32_t bf[2][4];
#pragma unroll
            for (int np = 0; np < 2; np++) {
                uint32_t addr = sB + (uint32_t)((warp_n * 32 + np * 16 + b_row) * 80
                                                + h16 * 32 + b_kb);
                ldsm_x4(bf[np], addr);
            }
#pragma unroll
            for (int mi = 0; mi < 4; mi++) {
                uint32_t af[4];
                uint32_t addr = sA + (uint32_t)((warp_m * 64 + mi * 16 + a_row) * 80
                                                + h16 * 32 + a_kb);
                ldsm_x4(af, addr);
                mma16816(acc[mi][0], af, bf[0][0], bf[0][1]);
                mma16816(acc[mi][1], af, bf[0][2], bf[0][3]);
                mma16816(acc[mi][2], af, bf[1][0], bf[1][1]);
                mma16816(acc[mi][3], af, bf[1][2], bf[1][3]);
            }
        }
        __syncthreads();
    }

    // ---------------- epilogue ----------------
    const int row0 = blockIdx.y * 128 + warp_m * 64;
    const int col0 = blockIdx.x * 128 + warp_n * 32;

    if (EPI == 1) {
#pragma unroll
        for (int mi = 0; mi < 4; mi++) {
#pragma unroll
            for (int ni = 0; ni < 4; ni++) {
                int col = col0 + ni * 8 + (lane & 3) * 2;
                float bx0 = bias[col], bx1 = bias[col + 1];
                int r0 = row0 + mi * 16 + (lane >> 2);
                float2 v0 = make_float2(acc[mi][ni][0] + bx0, acc[mi][ni][1] + bx1);
                float2 v1 = make_float2(acc[mi][ni][2] + bx0, acc[mi][ni][3] + bx1);
                *(float2*)(out + (size_t)r0 * 256 + col)       = v0;
                *(float2*)(out + (size_t)(r0 + 8) * 256 + col) = v1;
            }
        }
    } else {
#pragma unroll
        for (int mi = 0; mi < 4; mi++) {
#pragma unroll
            for (int ni = 0; ni < 4; ni++) {
#pragma unroll
                for (int id = 0; id < 4; id++) {
                    int row = row0 + mi * 16 + (lane >> 2) + 8 * (id >> 1);
                    int col = col0 + ni * 8 + (lane & 3) * 2 + (id & 1);
                    float v = acc[mi][ni][id] + bias[col];
                    int s = col % 3;
                    int hd = col / 3;            // h*32 + d
                    int h = hd >> 5, d = hd & 31;
                    int b = row / 49, n = row - b * 49;
                    size_t addr = (size_t)(b * NH + h) * (NTOK * HD) + n * HD + d;
                    if (s == 0)      g_Q[addr] = v * QSCALE;
                    else if (s == 1) g_K[addr] = v;
                    else             g_V[addr] = v;
                }
            }
        }
    }
}

// ======================= attention (per window-head CTA) ====================
__global__ __launch_bounds__(196)
void attn_kernel(const int* __restrict__ mask, const float* __restrict__ bias_table)
{
    __shared__ float sK[NTOK * HD];
    __shared__ float sV[NTOK * HD];
    __shared__ float sA[NTOK * NTOK];
    __shared__ float sBias[169];

    const int bh = blockIdx.x;
    const int b = bh >> 3, h = bh & 7;
    const int tid = threadIdx.x;

    const float* Qb = g_Q + (size_t)bh * NTOK * HD;
    const float* Kb = g_K + (size_t)bh * NTOK * HD;
    const float* Vb = g_V + (size_t)bh * NTOK * HD;

    for (int i = tid; i < NTOK * HD / 4; i += blockDim.x) {
        ((float4*)sK)[i] = ((const float4*)Kb)[i];
        ((float4*)sV)[i] = ((const float4*)Vb)[i];
    }
    for (int i = tid; i < 169; i += blockDim.x)
        sBias[i] = bias_table[i * NH + h];
    __syncthreads();

    {   // S = Q K^T + bias + mask
        const int q = tid >> 2;
        float qr[HD];
#pragma unroll
        for (int d4 = 0; d4 < HD / 4; d4++) {
            float4 v = ((const float4*)(Qb + q * HD))[d4];
            qr[d4 * 4 + 0] = v.x; qr[d4 * 4 + 1] = v.y;
            qr[d4 * 4 + 2] = v.z; qr[d4 * 4 + 3] = v.w;
        }
        const int qi = q / 7, qj = q - qi * 7;
        const int* mrow = mask + (size_t)b * NTOK * NTOK + q * NTOK;
        for (int k = (tid & 3); k < NTOK; k += 4) {
            float s = 0.f;
#pragma unroll
            for (int d4 = 0; d4 < HD / 4; d4++) {
                float4 kv = ((const float4*)(sK + k * HD))[d4];
                s = fmaf(qr[d4 * 4 + 0], kv.x, s);
                s = fmaf(qr[d4 * 4 + 1], kv.y, s);
                s = fmaf(qr[d4 * 4 + 2], kv.z, s);
                s = fmaf(qr[d4 * 4 + 3], kv.w, s);
            }
            int ki = k / 7, kj = k - ki * 7;
            s += sBias[(qi - ki + 6) * 13 + (qj - kj + 6)];
            s += (1.0f - (float)mrow[k]) * (-1e10f);
            sA[q * NTOK + k] = s;
        }
    }
    __syncthreads();

    if (tid < NTOK) {   // softmax row
        float* r = sA + tid * NTOK;
        float m = r[0];
#pragma unroll 7
        for (int k = 1; k < NTOK; k++) m = fmaxf(m, r[k]);
        float sum = 0.f;
#pragma unroll 7
        for (int k = 0; k < NTOK; k++) { float e = __expf(r[k] - m); r[k] = e; sum += e; }
        float inv = 1.0f / sum;
#pragma unroll 7
        for (int k = 0; k < NTOK; k++) r[k] *= inv;
    }
    __syncthreads();

    // O = P V -> ctx cat bf16 [hi | lo | hi], row = b*49+q, col = h*32+d
    __nv_bfloat16* crow = g_ccat + ((size_t)b * NTOK) * KCAT + h * HD;
    for (int e = tid; e < NTOK * HD; e += blockDim.x) {
        int qq = e >> 5, d = e & 31;
        float s = 0.f;
        const float* ar = sA + qq * NTOK;
#pragma unroll 7
        for (int k = 0; k < NTOK; k++)
            s = fmaf(ar[k], sV[k * HD + d], s);
        __nv_bfloat16 hv = __float2bfloat16(s);
        __nv_bfloat16 lv = __float2bfloat16(s - __bfloat162float(hv));
        __nv_bfloat16* p = crow + (size_t)qq * KCAT + d;
        p[0]   = hv;
        p[256] = lv;
        p[512] = hv;
    }
}

// ============================================================================
extern "C" void kernel_launch(void* const* d_in, const int* in_sizes, int n_in,
                              void* d_out, int out_size)
{
    const float* x       = (const float*)d_in[0];
    const int*   mask    = (const int*)d_in[1];
    const float* qkv_w   = (const float*)d_in[2];
    const float* qkv_b   = (const float*)d_in[3];
    const float* proj_w  = (const float*)d_in[4];
    const float* proj_b  = (const float*)d_in[5];
    const float* rel_tbl = (const float*)d_in[6];
    float* out = (float*)d_out;

    __nv_bfloat16 *xcat, *wq, *wp;
    cudaGetSymbolAddress((void**)&xcat, g_xcat);
    cudaGetSymbolAddress((void**)&wq, g_wq);
    cudaGetSymbolAddress((void**)&wp, g_wp);

    // pack inputs
    k_split_x<<<MTOT * 256 / 1024, 256>>>(x, xcat);
    k_split_w<<<768, 256>>>(qkv_w, wq, 768);
    k_split_w<<<256, 256>>>(proj_w, wp, 256);

    // QKV GEMM: 6 col tiles x 1568 row tiles (x fastest -> A reuse in L2)
    mma_gemm<0><<<dim3(6, MTOT / 128), 256>>>(qkv_b, nullptr);

    attn_kernel<<<BWIN * NH, 196>>>(mask, rel_tbl);

    // proj GEMM: 2 col tiles x 1568 row tiles
    mma_gemm<1><<<dim3(2, MTOT / 128), 256>>>(proj_b, out);
}

// round 4
// speedup vs baseline: 1.3654x; 1.0402x over previous
#include <cuda_runtime.h>
#include <cuda_bf16.h>
#include <cstdint>

#define BWIN 4096
#define NTOK 49
#define DIMV 256
#define NH   8
#define HD   32
#define MTOT (BWIN*NTOK)              /* 200704 */
#define KCAT 768                      /* 3 x 256 (hi|lo|hi) */
#define QSCALE 0.17677669529663687f   /* 32^-0.5 */

// ================= scratch (device globals; no allocation allowed) =========
__device__ __nv_bfloat16 g_xcat[(size_t)MTOT * KCAT];   // [hi | lo | hi]
__device__ __nv_bfloat16 g_ccat[(size_t)MTOT * KCAT];   // attention out, same layout
__device__ __nv_bfloat16 g_wq[768 * KCAT];              // [n][hi | hi | lo]
__device__ __nv_bfloat16 g_wp[256 * KCAT];
__device__ float g_Q[(size_t)BWIN * NH * NTOK * HD];
__device__ float g_K[(size_t)BWIN * NH * NTOK * HD];
__device__ float g_V[(size_t)BWIN * NH * NTOK * HD];

// ======================= helpers ===========================================
__device__ __forceinline__ uint32_t smem_u32(const void* p) {
    uint32_t a;
    asm("{ .reg .u64 t; cvta.to.shared.u64 t, %1; cvt.u32.u64 %0, t; }" : "=r"(a) : "l"(p));
    return a;
}
__device__ __forceinline__ void cp16(uint32_t sdst, const void* g) {
    asm volatile("cp.async.cg.shared.global [%0], [%1], 16;" :: "r"(sdst), "l"(g));
}
#define CP_COMMIT() asm volatile("cp.async.commit_group;" ::: "memory")

__device__ __forceinline__ void ldsm_x4(uint32_t (&r)[4], uint32_t addr) {
    asm volatile("ldmatrix.sync.aligned.m8n8.x4.shared.b16 {%0,%1,%2,%3}, [%4];"
                 : "=r"(r[0]), "=r"(r[1]), "=r"(r[2]), "=r"(r[3]) : "r"(addr));
}
__device__ __forceinline__ void mma16816(float (&d)[4], const uint32_t (&a)[4],
                                         uint32_t b0, uint32_t b1) {
    asm volatile("mma.sync.aligned.m16n8k16.row.col.f32.bf16.bf16.f32 "
                 "{%0,%1,%2,%3}, {%4,%5,%6,%7}, {%8,%9}, {%0,%1,%2,%3};"
                 : "+f"(d[0]), "+f"(d[1]), "+f"(d[2]), "+f"(d[3])
                 : "r"(a[0]), "r"(a[1]), "r"(a[2]), "r"(a[3]), "r"(b0), "r"(b1));
}

// ======================= split / pack kernels ==============================
__global__ __launch_bounds__(256) void k_split_x(const float* __restrict__ in,
                                                 __nv_bfloat16* __restrict__ cat) {
    size_t gi = ((size_t)blockIdx.x * 256 + threadIdx.x) * 4;
    size_t m = gi >> 8;
    int k = (int)(gi & 255);
    float4 v = *(const float4*)(in + gi);
    __nv_bfloat16 h0 = __float2bfloat16(v.x), h1 = __float2bfloat16(v.y);
    __nv_bfloat16 h2 = __float2bfloat16(v.z), h3 = __float2bfloat16(v.w);
    __nv_bfloat162 hA = __halves2bfloat162(h0, h1), hB = __halves2bfloat162(h2, h3);
    __nv_bfloat162 lA = __halves2bfloat162(__float2bfloat16(v.x - __bfloat162float(h0)),
                                           __float2bfloat16(v.y - __bfloat162float(h1)));
    __nv_bfloat162 lB = __halves2bfloat162(__float2bfloat16(v.z - __bfloat162float(h2)),
                                           __float2bfloat16(v.w - __bfloat162float(h3)));
    __nv_bfloat16* row = cat + m * KCAT;
    *(__nv_bfloat162*)(row + k)           = hA; *(__nv_bfloat162*)(row + k + 2)       = hB;
    *(__nv_bfloat162*)(row + 256 + k)     = lA; *(__nv_bfloat162*)(row + 256 + k + 2) = lB;
    *(__nv_bfloat162*)(row + 512 + k)     = hA; *(__nv_bfloat162*)(row + 512 + k + 2) = hB;
}

__global__ __launch_bounds__(256) void k_split_w(const float* __restrict__ w,
                                                 __nv_bfloat16* __restrict__ cat, int N) {
    int i = blockIdx.x * 256 + threadIdx.x;   // over 256*N
    int k = i / N, n = i - k * N;
    float v = w[i];
    __nv_bfloat16 h = __float2bfloat16(v);
    __nv_bfloat16 l = __float2bfloat16(v - __bfloat162float(h));
    __nv_bfloat16* row = cat + (size_t)n * KCAT;
    row[k] = h; row[256 + k] = h; row[512 + k] = l;
}

// ======================= HMMA GEMM =========================================
// C tile 128x128 = A'[M,768] * B'[N,768]^T, bf16, fp32 acc.
// BK=64, 3-stage cp.async pipeline, one barrier per K-iteration.
template<int EPI>
__global__ __launch_bounds__(256, 2) void mma_gemm(const float* __restrict__ bias,
                                                   float* __restrict__ out) {
    extern __shared__ char smem[];
    const uint32_t sb = smem_u32(smem);
    constexpr int PITCHB = 144;                   // 64 bf16 data + 8 pad, bytes
    constexpr uint32_t ATILE = 128 * PITCHB;      // 18432 B
    constexpr uint32_t STAGEB = 2 * ATILE;        // A + B
    constexpr int ITERS = 12;                     // 768 / 64

    const int tid = threadIdx.x;
    const int wid = tid >> 5, lane = tid & 31;
    const int warp_m = wid & 1, warp_n = wid >> 1;

    const __nv_bfloat16* gA = (EPI ? g_ccat : g_xcat) + (size_t)blockIdx.y * 128 * KCAT;
    const __nv_bfloat16* gB = (EPI ? g_wp   : g_wq)   + (size_t)blockIdx.x * 128 * KCAT;

    float acc[4][4][4];
#pragma unroll
    for (int a = 0; a < 4; a++)
#pragma unroll
        for (int b = 0; b < 4; b++)
#pragma unroll
            for (int c = 0; c < 4; c++) acc[a][b][c] = 0.f;

    auto load_stage = [&](int it, int s) {
        const int k0 = it * 64;
        const uint32_t st = sb + (uint32_t)s * STAGEB;
#pragma unroll
        for (int j = 0; j < 8; j++) {
            int cid = tid + j * 256;            // 0..2047
            int half = cid >> 10;               // 0=A, 1=B
            int r = (cid >> 3) & 127;
            int c = cid & 7;
            const __nv_bfloat16* src = (half ? gB : gA) + (size_t)r * KCAT + k0 + c * 8;
            cp16(st + (uint32_t)half * ATILE + (uint32_t)(r * PITCHB + c * 16), src);
        }
        CP_COMMIT();
    };

    // ldmatrix lane address components
    const int a_row = (lane & 7) + 8 * ((lane >> 3) & 1);
    const int a_kb  = ((lane >> 4) & 1) * 16;
    const int b_row = (lane & 7) + 8 * ((lane >> 4) & 1);
    const int b_kb  = ((lane >> 3) & 1) * 16;

    load_stage(0, 0);
    load_stage(1, 1);

    int s = 0;
#pragma unroll 1
    for (int it = 0; it < ITERS; ++it) {
        if (it >= ITERS - 2)
            asm volatile("cp.async.wait_group 0;" ::: "memory");
        else
            asm volatile("cp.async.wait_group 1;" ::: "memory");
        __syncthreads();

        if (it + 2 < ITERS) {
            int s2 = s + 2; if (s2 >= 3) s2 -= 3;
            load_stage(it + 2, s2);
        }

        const uint32_t sA = sb + (uint32_t)s * STAGEB;
        const uint32_t sB = sA + ATILE;
#pragma unroll
        for (int h16 = 0; h16 < 4; h16++) {
            uint32_t bf[2][4];
#pragma unroll
            for (int np = 0; np < 2; np++) {
                uint32_t addr = sB + (uint32_t)((warp_n * 32 + np * 16 + b_row) * PITCHB
                                                + h16 * 32 + b_kb);
                ldsm_x4(bf[np], addr);
            }
#pragma unroll
            for (int mi = 0; mi < 4; mi++) {
                uint32_t af[4];
                uint32_t addr = sA + (uint32_t)((warp_m * 64 + mi * 16 + a_row) * PITCHB
                                                + h16 * 32 + a_kb);
                ldsm_x4(af, addr);
                mma16816(acc[mi][0], af, bf[0][0], bf[0][1]);
                mma16816(acc[mi][1], af, bf[0][2], bf[0][3]);
                mma16816(acc[mi][2], af, bf[1][0], bf[1][1]);
                mma16816(acc[mi][3], af, bf[1][2], bf[1][3]);
            }
        }
        if (++s >= 3) s = 0;
    }

    // ---------------- epilogue ----------------
    const int row0 = blockIdx.y * 128 + warp_m * 64;
    const int col0 = blockIdx.x * 128 + warp_n * 32;

    if (EPI == 1) {
#pragma unroll
        for (int mi = 0; mi < 4; mi++) {
#pragma unroll
            for (int ni = 0; ni < 4; ni++) {
                int col = col0 + ni * 8 + (lane & 3) * 2;
                float bx0 = bias[col], bx1 = bias[col + 1];
                int r0 = row0 + mi * 16 + (lane >> 2);
                float2 v0 = make_float2(acc[mi][ni][0] + bx0, acc[mi][ni][1] + bx1);
                float2 v1 = make_float2(acc[mi][ni][2] + bx0, acc[mi][ni][3] + bx1);
                *(float2*)(out + (size_t)r0 * 256 + col)       = v0;
                *(float2*)(out + (size_t)(r0 + 8) * 256 + col) = v1;
            }
        }
    } else {
#pragma unroll
        for (int mi = 0; mi < 4; mi++) {
#pragma unroll
            for (int ni = 0; ni < 4; ni++) {
#pragma unroll
                for (int id = 0; id < 4; id++) {
                    int row = row0 + mi * 16 + (lane >> 2) + 8 * (id >> 1);
                    int col = col0 + ni * 8 + (lane & 3) * 2 + (id & 1);
                    float v = acc[mi][ni][id] + bias[col];
                    int s2 = col % 3;
                    int hd = col / 3;
                    int h = hd >> 5, d = hd & 31;
                    int b = row / 49, n = row - b * 49;
                    size_t addr = (size_t)(b * NH + h) * (NTOK * HD) + n * HD + d;
                    if (s2 == 0)      g_Q[addr] = v * QSCALE;
                    else if (s2 == 1) g_K[addr] = v;
                    else              g_V[addr] = v;
                }
            }
        }
    }
}

// ======================= attention (per window-head CTA) ====================
__global__ __launch_bounds__(196)
void attn_kernel(const int* __restrict__ mask, const float* __restrict__ bias_table)
{
    __shared__ float sK[NTOK * HD];
    __shared__ float sV[NTOK * HD];
    __shared__ float sA[NTOK * NTOK];
    __shared__ float sBias[169];

    const int bh = blockIdx.x;
    const int b = bh >> 3, h = bh & 7;
    const int tid = threadIdx.x;

    const float* Qb = g_Q + (size_t)bh * NTOK * HD;
    const float* Kb = g_K + (size_t)bh * NTOK * HD;
    const float* Vb = g_V + (size_t)bh * NTOK * HD;

    for (int i = tid; i < NTOK * HD / 4; i += blockDim.x) {
        ((float4*)sK)[i] = ((const float4*)Kb)[i];
        ((float4*)sV)[i] = ((const float4*)Vb)[i];
    }
    for (int i = tid; i < 169; i += blockDim.x)
        sBias[i] = bias_table[i * NH + h];
    __syncthreads();

    {   // S = Q K^T + bias + mask
        const int q = tid >> 2;
        float qr[HD];
#pragma unroll
        for (int d4 = 0; d4 < HD / 4; d4++) {
            float4 v = ((const float4*)(Qb + q * HD))[d4];
            qr[d4 * 4 + 0] = v.x; qr[d4 * 4 + 1] = v.y;
            qr[d4 * 4 + 2] = v.z; qr[d4 * 4 + 3] = v.w;
        }
        const int qi = q / 7, qj = q - qi * 7;
        const int* mrow = mask + (size_t)b * NTOK * NTOK + q * NTOK;
        for (int k = (tid & 3); k < NTOK; k += 4) {
            float s = 0.f;
#pragma unroll
            for (int d4 = 0; d4 < HD / 4; d4++) {
                float4 kv = ((const float4*)(sK + k * HD))[d4];
                s = fmaf(qr[d4 * 4 + 0], kv.x, s);
                s = fmaf(qr[d4 * 4 + 1], kv.y, s);
                s = fmaf(qr[d4 * 4 + 2], kv.z, s);
                s = fmaf(qr[d4 * 4 + 3], kv.w, s);
            }
            int ki = k / 7, kj = k - ki * 7;
            s += sBias[(qi - ki + 6) * 13 + (qj - kj + 6)];
            s += (1.0f - (float)mrow[k]) * (-1e10f);
            sA[q * NTOK + k] = s;
        }
    }
    __syncthreads();

    if (tid < NTOK) {   // softmax row
        float* r = sA + tid * NTOK;
        float m = r[0];
#pragma unroll 7
        for (int k = 1; k < NTOK; k++) m = fmaxf(m, r[k]);
        float sum = 0.f;
#pragma unroll 7
        for (int k = 0; k < NTOK; k++) { float e = __expf(r[k] - m); r[k] = e; sum += e; }
        float inv = 1.0f / sum;
#pragma unroll 7
        for (int k = 0; k < NTOK; k++) r[k] *= inv;
    }
    __syncthreads();

    // O = P V -> ctx cat bf16 [hi | lo | hi]
    __nv_bfloat16* crow = g_ccat + ((size_t)b * NTOK) * KCAT + h * HD;
    for (int e = tid; e < NTOK * HD; e += blockDim.x) {
        int qq = e >> 5, d = e & 31;
        float s = 0.f;
        const float* ar = sA + qq * NTOK;
#pragma unroll 7
        for (int k = 0; k < NTOK; k++)
            s = fmaf(ar[k], sV[k * HD + d], s);
        __nv_bfloat16 hv = __float2bfloat16(s);
        __nv_bfloat16 lv = __float2bfloat16(s - __bfloat162float(hv));
        __nv_bfloat16* p = crow + (size_t)qq * KCAT + d;
        p[0]   = hv;
        p[256] = lv;
        p[512] = hv;
    }
}

// ============================================================================
extern "C" void kernel_launch(void* const* d_in, const int* in_sizes, int n_in,
                              void* d_out, int out_size)
{
    const float* x       = (const float*)d_in[0];
    const int*   mask    = (const int*)d_in[1];
    const float* qkv_w   = (const float*)d_in[2];
    const float* qkv_b   = (const float*)d_in[3];
    const float* proj_w  = (const float*)d_in[4];
    const float* proj_b  = (const float*)d_in[5];
    const float* rel_tbl = (const float*)d_in[6];
    float* out = (float*)d_out;

    __nv_bfloat16 *xcat, *wq, *wp;
    cudaGetSymbolAddress((void**)&xcat, g_xcat);
    cudaGetSymbolAddress((void**)&wq, g_wq);
    cudaGetSymbolAddress((void**)&wp, g_wp);

    constexpr int SMEMB = 3 * 2 * 128 * 144;   // 110592
    cudaFuncSetAttribute(mma_gemm<0>, cudaFuncAttributeMaxDynamicSharedMemorySize, SMEMB);
    cudaFuncSetAttribute(mma_gemm<1>, cudaFuncAttributeMaxDynamicSharedMemorySize, SMEMB);

    // pack inputs
    k_split_x<<<MTOT * 256 / 1024, 256>>>(x, xcat);
    k_split_w<<<768, 256>>>(qkv_w, wq, 768);
    k_split_w<<<256, 256>>>(proj_w, wp, 256);

    // QKV GEMM
    mma_gemm<0><<<dim3(6, MTOT / 128), 256, SMEMB>>>(qkv_b, nullptr);

    attn_kernel<<<BWIN * NH, 196>>>(mask, rel_tbl);

    // proj GEMM
    mma_gemm<1><<<dim3(2, MTOT / 128), 256, SMEMB>>>(proj_b, out);
}

// round 5
// speedup vs baseline: 1.4405x; 1.0550x over previous
#include <cuda_runtime.h>
#include <cuda_bf16.h>
#include <cstdint>

#define BWIN 4096
#define NTOK 49
#define DIMV 256
#define NH   8
#define HD   32
#define MTOT (BWIN*NTOK)              /* 200704 */
#define QSCALE 0.17677669529663687f   /* 32^-0.5 */

// ================= scratch (device globals; no allocation allowed) =========
__device__ __nv_bfloat16 g_xhi[(size_t)MTOT * DIMV];
__device__ __nv_bfloat16 g_xlo[(size_t)MTOT * DIMV];
__device__ __nv_bfloat16 g_chi[(size_t)MTOT * DIMV];
__device__ __nv_bfloat16 g_clo[(size_t)MTOT * DIMV];
__device__ __nv_bfloat16 g_wqh[768 * 256];
__device__ __nv_bfloat16 g_wql[768 * 256];
__device__ __nv_bfloat16 g_wph[256 * 256];
__device__ __nv_bfloat16 g_wpl[256 * 256];
__device__ float g_Q[(size_t)BWIN * NH * NTOK * HD];
__device__ float g_K[(size_t)BWIN * NH * NTOK * HD];
__device__ float g_V[(size_t)BWIN * NH * NTOK * HD];

// ======================= helpers ===========================================
__device__ __forceinline__ uint32_t smem_u32(const void* p) {
    uint32_t a;
    asm("{ .reg .u64 t; cvta.to.shared.u64 t, %1; cvt.u32.u64 %0, t; }" : "=r"(a) : "l"(p));
    return a;
}
__device__ __forceinline__ void cp16(uint32_t sdst, const void* g) {
    asm volatile("cp.async.cg.shared.global [%0], [%1], 16;" :: "r"(sdst), "l"(g));
}
#define CP_COMMIT() asm volatile("cp.async.commit_group;" ::: "memory")

__device__ __forceinline__ void ldsm_x4(uint32_t (&r)[4], uint32_t addr) {
    asm volatile("ldmatrix.sync.aligned.m8n8.x4.shared.b16 {%0,%1,%2,%3}, [%4];"
                 : "=r"(r[0]), "=r"(r[1]), "=r"(r[2]), "=r"(r[3]) : "r"(addr));
}
__device__ __forceinline__ void mma16816(float (&d)[4], const uint32_t (&a)[4],
                                         uint32_t b0, uint32_t b1) {
    asm volatile("mma.sync.aligned.m16n8k16.row.col.f32.bf16.bf16.f32 "
                 "{%0,%1,%2,%3}, {%4,%5,%6,%7}, {%8,%9}, {%0,%1,%2,%3};"
                 : "+f"(d[0]), "+f"(d[1]), "+f"(d[2]), "+f"(d[3])
                 : "r"(a[0]), "r"(a[1]), "r"(a[2]), "r"(a[3]), "r"(b0), "r"(b1));
}

// ======================= split / pack kernels ==============================
__global__ __launch_bounds__(256) void k_split_x(const float* __restrict__ in,
                                                 __nv_bfloat16* __restrict__ hi,
                                                 __nv_bfloat16* __restrict__ lo) {
    size_t gi = ((size_t)blockIdx.x * 256 + threadIdx.x) * 4;
    float4 v = *(const float4*)(in + gi);
    __nv_bfloat16 h0 = __float2bfloat16(v.x), h1 = __float2bfloat16(v.y);
    __nv_bfloat16 h2 = __float2bfloat16(v.z), h3 = __float2bfloat16(v.w);
    __nv_bfloat162 hA = __halves2bfloat162(h0, h1), hB = __halves2bfloat162(h2, h3);
    __nv_bfloat162 lA = __halves2bfloat162(__float2bfloat16(v.x - __bfloat162float(h0)),
                                           __float2bfloat16(v.y - __bfloat162float(h1)));
    __nv_bfloat162 lB = __halves2bfloat162(__float2bfloat16(v.z - __bfloat162float(h2)),
                                           __float2bfloat16(v.w - __bfloat162float(h3)));
    *(__nv_bfloat162*)(hi + gi)     = hA; *(__nv_bfloat162*)(hi + gi + 2) = hB;
    *(__nv_bfloat162*)(lo + gi)     = lA; *(__nv_bfloat162*)(lo + gi + 2) = lB;
}

// w [256,N] fp32 -> whi/wlo [N,256] bf16 (k-major, transposed)
__global__ __launch_bounds__(256) void k_split_w(const float* __restrict__ w,
                                                 __nv_bfloat16* __restrict__ hi,
                                                 __nv_bfloat16* __restrict__ lo, int N) {
    int i = blockIdx.x * 256 + threadIdx.x;   // over 256*N
    int k = i / N, n = i - k * N;
    float v = w[i];
    __nv_bfloat16 h = __float2bfloat16(v);
    hi[(size_t)n * 256 + k] = h;
    lo[(size_t)n * 256 + k] = __float2bfloat16(v - __bfloat162float(h));
}

// ======================= HMMA GEMM =========================================
// C tile 128x128 = (Ahi+Alo)[M,256] * (Bhi+Blo)[N,256]^T, 3-term compensated.
// BK=32, 2-stage cp.async double buffer, fragment reuse across terms.
template<int EPI>
__global__ __launch_bounds__(256, 2) void mma_gemm(const float* __restrict__ bias,
                                                   float* __restrict__ out) {
    extern __shared__ char smem[];
    const uint32_t sb = smem_u32(smem);
    constexpr int PITCH = 80;                     // 32 bf16 data + 8 pad, bytes
    constexpr uint32_t TILE = 128 * PITCH;        // 10240 B
    constexpr uint32_t STAGE = 4 * TILE;          // Ahi, Alo, Bhi, Blo
    constexpr int ITERS = 8;                      // 256 / 32

    const int tid = threadIdx.x;
    const int wid = tid >> 5, lane = tid & 31;
    const int warp_m = wid & 1, warp_n = wid >> 1;

    const __nv_bfloat16* gAh = (EPI ? g_chi : g_xhi) + (size_t)blockIdx.y * 128 * 256;
    const __nv_bfloat16* gAl = (EPI ? g_clo : g_xlo) + (size_t)blockIdx.y * 128 * 256;
    const __nv_bfloat16* gBh = (EPI ? g_wph : g_wqh) + (size_t)blockIdx.x * 128 * 256;
    const __nv_bfloat16* gBl = (EPI ? g_wpl : g_wql) + (size_t)blockIdx.x * 128 * 256;

    float acc[4][4][4];
#pragma unroll
    for (int a = 0; a < 4; a++)
#pragma unroll
        for (int b = 0; b < 4; b++)
#pragma unroll
            for (int c = 0; c < 4; c++) acc[a][b][c] = 0.f;

    const int lr = tid >> 2;          // 0..63  row part
    const int lc = tid & 3;           // 0..3   16B col
    auto load_stage = [&](int it, int s) {
        const int k0 = it * 32;
        const uint32_t st = sb + (uint32_t)s * STAGE;
#pragma unroll
        for (int j = 0; j < 8; j++) {
            const __nv_bfloat16* base = (j < 2) ? gAh : (j < 4) ? gAl : (j < 6) ? gBh : gBl;
            int r = lr + (j & 1) * 64;
            cp16(st + (uint32_t)(j >> 1) * TILE + (uint32_t)(r * PITCH + lc * 16),
                 base + (size_t)r * 256 + k0 + lc * 8);
        }
        CP_COMMIT();
    };

    // ldmatrix lane address components
    const int a_row = (lane & 7) + 8 * ((lane >> 3) & 1);
    const int a_kb  = ((lane >> 4) & 1) * 16;
    const int b_row = (lane & 7) + 8 * ((lane >> 4) & 1);
    const int b_kb  = ((lane >> 3) & 1) * 16;

    load_stage(0, 0);

    int s = 0;
#pragma unroll 1
    for (int it = 0; it < ITERS; ++it) {
        asm volatile("cp.async.wait_group 0;" ::: "memory");
        __syncthreads();
        if (it + 1 < ITERS) load_stage(it + 1, s ^ 1);

        const uint32_t sAh = sb + (uint32_t)s * STAGE;
        const uint32_t sAl = sAh + TILE;
        const uint32_t sBh = sAl + TILE;
        const uint32_t sBl = sBh + TILE;
#pragma unroll
        for (int h16 = 0; h16 < 2; h16++) {
            const int kb = h16 * 32;
            uint32_t bhi[2][4], blo[2][4];
#pragma unroll
            for (int np = 0; np < 2; np++) {
                uint32_t boff = (uint32_t)((warp_n * 32 + np * 16 + b_row) * PITCH + kb + b_kb);
                ldsm_x4(bhi[np], sBh + boff);
                ldsm_x4(blo[np], sBl + boff);
            }
            uint32_t ahi[4][4], alo[4][4];
#pragma unroll
            for (int mi = 0; mi < 4; mi++) {
                uint32_t aoff = (uint32_t)((warp_m * 64 + mi * 16 + a_row) * PITCH + kb + a_kb);
                ldsm_x4(ahi[mi], sAh + aoff);
                ldsm_x4(alo[mi], sAl + aoff);
            }
            // term 1: hi*hi
#pragma unroll
            for (int mi = 0; mi < 4; mi++) {
                mma16816(acc[mi][0], ahi[mi], bhi[0][0], bhi[0][1]);
                mma16816(acc[mi][1], ahi[mi], bhi[0][2], bhi[0][3]);
                mma16816(acc[mi][2], ahi[mi], bhi[1][0], bhi[1][1]);
                mma16816(acc[mi][3], ahi[mi], bhi[1][2], bhi[1][3]);
            }
            // term 2: hi*lo
#pragma unroll
            for (int mi = 0; mi < 4; mi++) {
                mma16816(acc[mi][0], ahi[mi], blo[0][0], blo[0][1]);
                mma16816(acc[mi][1], ahi[mi], blo[0][2], blo[0][3]);
                mma16816(acc[mi][2], ahi[mi], blo[1][0], blo[1][1]);
                mma16816(acc[mi][3], ahi[mi], blo[1][2], blo[1][3]);
            }
            // term 3: lo*hi
#pragma unroll
            for (int mi = 0; mi < 4; mi++) {
                mma16816(acc[mi][0], alo[mi], bhi[0][0], bhi[0][1]);
                mma16816(acc[mi][1], alo[mi], bhi[0][2], bhi[0][3]);
                mma16816(acc[mi][2], alo[mi], bhi[1][0], bhi[1][1]);
                mma16816(acc[mi][3], alo[mi], bhi[1][2], bhi[1][3]);
            }
        }
        s ^= 1;
    }

    // ---------------- epilogue ----------------
    const int row0 = blockIdx.y * 128 + warp_m * 64;
    const int col0 = blockIdx.x * 128 + warp_n * 32;

    if (EPI == 1) {
#pragma unroll
        for (int mi = 0; mi < 4; mi++) {
#pragma unroll
            for (int ni = 0; ni < 4; ni++) {
                int col = col0 + ni * 8 + (lane & 3) * 2;
                float bx0 = bias[col], bx1 = bias[col + 1];
                int r0 = row0 + mi * 16 + (lane >> 2);
                float2 v0 = make_float2(acc[mi][ni][0] + bx0, acc[mi][ni][1] + bx1);
                float2 v1 = make_float2(acc[mi][ni][2] + bx0, acc[mi][ni][3] + bx1);
                *(float2*)(out + (size_t)r0 * 256 + col)       = v0;
                *(float2*)(out + (size_t)(r0 + 8) * 256 + col) = v1;
            }
        }
    } else {
#pragma unroll
        for (int mi = 0; mi < 4; mi++) {
#pragma unroll
            for (int ni = 0; ni < 4; ni++) {
#pragma unroll
                for (int id = 0; id < 4; id++) {
                    int row = row0 + mi * 16 + (lane >> 2) + 8 * (id >> 1);
                    int col = col0 + ni * 8 + (lane & 3) * 2 + (id & 1);
                    float v = acc[mi][ni][id] + bias[col];
                    int s2 = col % 3;
                    int hd = col / 3;
                    int h = hd >> 5, d = hd & 31;
                    int b = row / 49, n = row - b * 49;
                    size_t addr = (size_t)(b * NH + h) * (NTOK * HD) + n * HD + d;
                    if (s2 == 0)      g_Q[addr] = v * QSCALE;
                    else if (s2 == 1) g_K[addr] = v;
                    else              g_V[addr] = v;
                }
            }
        }
    }
}

// ======================= attention (per window-head CTA) ====================
__global__ __launch_bounds__(196)
void attn_kernel(const int* __restrict__ mask, const float* __restrict__ bias_table)
{
    __shared__ float sK[NTOK * HD];
    __shared__ float sV[NTOK * HD];
    __shared__ float sA[NTOK * NTOK];
    __shared__ float sBias[169];

    const int bh = blockIdx.x;
    const int b = bh >> 3, h = bh & 7;
    const int tid = threadIdx.x;

    const float* Qb = g_Q + (size_t)bh * NTOK * HD;
    const float* Kb = g_K + (size_t)bh * NTOK * HD;
    const float* Vb = g_V + (size_t)bh * NTOK * HD;

    for (int i = tid; i < NTOK * HD / 4; i += blockDim.x) {
        ((float4*)sK)[i] = ((const float4*)Kb)[i];
        ((float4*)sV)[i] = ((const float4*)Vb)[i];
    }
    for (int i = tid; i < 169; i += blockDim.x)
        sBias[i] = bias_table[i * NH + h];
    __syncthreads();

    {   // S = Q K^T + bias + mask
        const int q = tid >> 2;
        float qr[HD];
#pragma unroll
        for (int d4 = 0; d4 < HD / 4; d4++) {
            float4 v = ((const float4*)(Qb + q * HD))[d4];
            qr[d4 * 4 + 0] = v.x; qr[d4 * 4 + 1] = v.y;
            qr[d4 * 4 + 2] = v.z; qr[d4 * 4 + 3] = v.w;
        }
        const int qi = q / 7, qj = q - qi * 7;
        const int* mrow = mask + (size_t)b * NTOK * NTOK + q * NTOK;
        for (int k = (tid & 3); k < NTOK; k += 4) {
            float s = 0.f;
#pragma unroll
            for (int d4 = 0; d4 < HD / 4; d4++) {
                float4 kv = ((const float4*)(sK + k * HD))[d4];
                s = fmaf(qr[d4 * 4 + 0], kv.x, s);
                s = fmaf(qr[d4 * 4 + 1], kv.y, s);
                s = fmaf(qr[d4 * 4 + 2], kv.z, s);
                s = fmaf(qr[d4 * 4 + 3], kv.w, s);
            }
            int ki = k / 7, kj = k - ki * 7;
            s += sBias[(qi - ki + 6) * 13 + (qj - kj + 6)];
            s += (1.0f - (float)mrow[k]) * (-1e10f);
            sA[q * NTOK + k] = s;
        }
    }
    __syncthreads();

    if (tid < NTOK) {   // softmax row
        float* r = sA + tid * NTOK;
        float m = r[0];
#pragma unroll 7
        for (int k = 1; k < NTOK; k++) m = fmaxf(m, r[k]);
        float sum = 0.f;
#pragma unroll 7
        for (int k = 0; k < NTOK; k++) { float e = __expf(r[k] - m); r[k] = e; sum += e; }
        float inv = 1.0f / sum;
#pragma unroll 7
        for (int k = 0; k < NTOK; k++) r[k] *= inv;
    }
    __syncthreads();

    // O = P V -> chi/clo, row = b*49+q, col = h*32+d
    __nv_bfloat16* chiw = g_chi + ((size_t)b * NTOK) * DIMV + h * HD;
    __nv_bfloat16* clow = g_clo + ((size_t)b * NTOK) * DIMV + h * HD;
    for (int e = tid; e < NTOK * HD; e += blockDim.x) {
        int qq = e >> 5, d = e & 31;
        float s = 0.f;
        const float* ar = sA + qq * NTOK;
#pragma unroll 7
        for (int k = 0; k < NTOK; k++)
            s = fmaf(ar[k], sV[k * HD + d], s);
        __nv_bfloat16 hv = __float2bfloat16(s);
        chiw[(size_t)qq * DIMV + d] = hv;
        clow[(size_t)qq * DIMV + d] = __float2bfloat16(s - __bfloat162float(hv));
    }
}

// ============================================================================
extern "C" void kernel_launch(void* const* d_in, const int* in_sizes, int n_in,
                              void* d_out, int out_size)
{
    const float* x       = (const float*)d_in[0];
    const int*   mask    = (const int*)d_in[1];
    const float* qkv_w   = (const float*)d_in[2];
    const float* qkv_b   = (const float*)d_in[3];
    const float* proj_w  = (const float*)d_in[4];
    const float* proj_b  = (const float*)d_in[5];
    const float* rel_tbl = (const float*)d_in[6];
    float* out = (float*)d_out;

    __nv_bfloat16 *xhi, *xlo, *wqh, *wql, *wph, *wpl;
    cudaGetSymbolAddress((void**)&xhi, g_xhi);
    cudaGetSymbolAddress((void**)&xlo, g_xlo);
    cudaGetSymbolAddress((void**)&wqh, g_wqh);
    cudaGetSymbolAddress((void**)&wql, g_wql);
    cudaGetSymbolAddress((void**)&wph, g_wph);
    cudaGetSymbolAddress((void**)&wpl, g_wpl);

    constexpr int SMEMB = 2 * 4 * 128 * 80;    // 81920
    cudaFuncSetAttribute(mma_gemm<0>, cudaFuncAttributeMaxDynamicSharedMemorySize, SMEMB);
    cudaFuncSetAttribute(mma_gemm<1>, cudaFuncAttributeMaxDynamicSharedMemorySize, SMEMB);

    // pack inputs
    k_split_x<<<MTOT * 256 / 1024, 256>>>(x, xhi, xlo);
    k_split_w<<<768, 256>>>(qkv_w, wqh, wql, 768);
    k_split_w<<<256, 256>>>(proj_w, wph, wpl, 256);

    // QKV GEMM
    mma_gemm<0><<<dim3(6, MTOT / 128), 256, SMEMB>>>(qkv_b, nullptr);

    attn_kernel<<<BWIN * NH, 196>>>(mask, rel_tbl);

    // proj GEMM
    mma_gemm<1><<<dim3(2, MTOT / 128), 256, SMEMB>>>(proj_b, out);
}

// round 6
// speedup vs baseline: 2.0728x; 1.4389x over previous
#include <cuda_runtime.h>
#include <cuda_bf16.h>
#include <cstdint>

#define BWIN 4096
#define NTOK 49
#define DIMV 256
#define NH   8
#define HD   32
#define MTOT (BWIN*NTOK)              /* 200704 */
#define QSCALE 0.17677669529663687f   /* 32^-0.5 */

// ================= scratch (device globals; no allocation allowed) =========
__device__ __nv_bfloat16 g_xhi[(size_t)MTOT * DIMV];
__device__ __nv_bfloat16 g_xlo[(size_t)MTOT * DIMV];
__device__ __nv_bfloat16 g_chi[(size_t)MTOT * DIMV];
__device__ __nv_bfloat16 g_clo[(size_t)MTOT * DIMV];
__device__ __nv_bfloat16 g_wqh[768 * 256];
__device__ __nv_bfloat16 g_wql[768 * 256];
__device__ __nv_bfloat16 g_wph[256 * 256];
__device__ __nv_bfloat16 g_wpl[256 * 256];
__device__ float g_Q[(size_t)BWIN * NH * NTOK * HD];
__device__ float g_K[(size_t)BWIN * NH * NTOK * HD];
__device__ float g_V[(size_t)BWIN * NH * NTOK * HD];

// ======================= helpers ===========================================
__device__ __forceinline__ uint32_t smem_u32(const void* p) {
    uint32_t a;
    asm("{ .reg .u64 t; cvta.to.shared.u64 t, %1; cvt.u32.u64 %0, t; }" : "=r"(a) : "l"(p));
    return a;
}
__device__ __forceinline__ void cp16(uint32_t sdst, const void* g) {
    asm volatile("cp.async.cg.shared.global [%0], [%1], 16;" :: "r"(sdst), "l"(g));
}
#define CP_COMMIT() asm volatile("cp.async.commit_group;" ::: "memory")

__device__ __forceinline__ void ldsm_x4(uint32_t (&r)[4], uint32_t addr) {
    asm volatile("ldmatrix.sync.aligned.m8n8.x4.shared.b16 {%0,%1,%2,%3}, [%4];"
                 : "=r"(r[0]), "=r"(r[1]), "=r"(r[2]), "=r"(r[3]) : "r"(addr));
}
__device__ __forceinline__ void mma16816(float (&d)[4], const uint32_t (&a)[4],
                                         uint32_t b0, uint32_t b1) {
    asm volatile("mma.sync.aligned.m16n8k16.row.col.f32.bf16.bf16.f32 "
                 "{%0,%1,%2,%3}, {%4,%5,%6,%7}, {%8,%9}, {%0,%1,%2,%3};"
                 : "+f"(d[0]), "+f"(d[1]), "+f"(d[2]), "+f"(d[3])
                 : "r"(a[0]), "r"(a[1]), "r"(a[2]), "r"(a[3]), "r"(b0), "r"(b1));
}

// ======================= split / pack kernels ==============================
__global__ __launch_bounds__(256) void k_split_x(const float* __restrict__ in,
                                                 __nv_bfloat16* __restrict__ hi,
                                                 __nv_bfloat16* __restrict__ lo) {
    size_t gi = ((size_t)blockIdx.x * 256 + threadIdx.x) * 4;
    float4 v = *(const float4*)(in + gi);
    __nv_bfloat16 h0 = __float2bfloat16(v.x), h1 = __float2bfloat16(v.y);
    __nv_bfloat16 h2 = __float2bfloat16(v.z), h3 = __float2bfloat16(v.w);
    __nv_bfloat162 hA = __halves2bfloat162(h0, h1), hB = __halves2bfloat162(h2, h3);
    __nv_bfloat162 lA = __halves2bfloat162(__float2bfloat16(v.x - __bfloat162float(h0)),
                                           __float2bfloat16(v.y - __bfloat162float(h1)));
    __nv_bfloat162 lB = __halves2bfloat162(__float2bfloat16(v.z - __bfloat162float(h2)),
                                           __float2bfloat16(v.w - __bfloat162float(h3)));
    *(__nv_bfloat162*)(hi + gi)     = hA; *(__nv_bfloat162*)(hi + gi + 2) = hB;
    *(__nv_bfloat162*)(lo + gi)     = lA; *(__nv_bfloat162*)(lo + gi + 2) = lB;
}

__global__ __launch_bounds__(256) void k_split_w(const float* __restrict__ w,
                                                 __nv_bfloat16* __restrict__ hi,
                                                 __nv_bfloat16* __restrict__ lo, int N) {
    int i = blockIdx.x * 256 + threadIdx.x;   // over 256*N
    int k = i / N, n = i - k * N;
    float v = w[i];
    __nv_bfloat16 h = __float2bfloat16(v);
    hi[(size_t)n * 256 + k] = h;
    lo[(size_t)n * 256 + k] = __float2bfloat16(v - __bfloat162float(h));
}

// ======================= HMMA GEMM (unchanged from R5) =====================
template<int EPI>
__global__ __launch_bounds__(256, 2) void mma_gemm(const float* __restrict__ bias,
                                                   float* __restrict__ out) {
    extern __shared__ char smem[];
    const uint32_t sb = smem_u32(smem);
    constexpr int PITCH = 80;
    constexpr uint32_t TILE = 128 * PITCH;
    constexpr uint32_t STAGE = 4 * TILE;
    constexpr int ITERS = 8;

    const int tid = threadIdx.x;
    const int wid = tid >> 5, lane = tid & 31;
    const int warp_m = wid & 1, warp_n = wid >> 1;

    const __nv_bfloat16* gAh = (EPI ? g_chi : g_xhi) + (size_t)blockIdx.y * 128 * 256;
    const __nv_bfloat16* gAl = (EPI ? g_clo : g_xlo) + (size_t)blockIdx.y * 128 * 256;
    const __nv_bfloat16* gBh = (EPI ? g_wph : g_wqh) + (size_t)blockIdx.x * 128 * 256;
    const __nv_bfloat16* gBl = (EPI ? g_wpl : g_wql) + (size_t)blockIdx.x * 128 * 256;

    float acc[4][4][4];
#pragma unroll
    for (int a = 0; a < 4; a++)
#pragma unroll
        for (int b = 0; b < 4; b++)
#pragma unroll
            for (int c = 0; c < 4; c++) acc[a][b][c] = 0.f;

    const int lr = tid >> 2;
    const int lc = tid & 3;
    auto load_stage = [&](int it, int s) {
        const int k0 = it * 32;
        const uint32_t st = sb + (uint32_t)s * STAGE;
#pragma unroll
        for (int j = 0; j < 8; j++) {
            const __nv_bfloat16* base = (j < 2) ? gAh : (j < 4) ? gAl : (j < 6) ? gBh : gBl;
            int r = lr + (j & 1) * 64;
            cp16(st + (uint32_t)(j >> 1) * TILE + (uint32_t)(r * PITCH + lc * 16),
                 base + (size_t)r * 256 + k0 + lc * 8);
        }
        CP_COMMIT();
    };

    const int a_row = (lane & 7) + 8 * ((lane >> 3) & 1);
    const int a_kb  = ((lane >> 4) & 1) * 16;
    const int b_row = (lane & 7) + 8 * ((lane >> 4) & 1);
    const int b_kb  = ((lane >> 3) & 1) * 16;

    load_stage(0, 0);

    int s = 0;
#pragma unroll 1
    for (int it = 0; it < ITERS; ++it) {
        asm volatile("cp.async.wait_group 0;" ::: "memory");
        __syncthreads();
        if (it + 1 < ITERS) load_stage(it + 1, s ^ 1);

        const uint32_t sAh = sb + (uint32_t)s * STAGE;
        const uint32_t sAl = sAh + TILE;
        const uint32_t sBh = sAl + TILE;
        const uint32_t sBl = sBh + TILE;
#pragma unroll
        for (int h16 = 0; h16 < 2; h16++) {
            const int kb = h16 * 32;
            uint32_t bhi[2][4], blo[2][4];
#pragma unroll
            for (int np = 0; np < 2; np++) {
                uint32_t boff = (uint32_t)((warp_n * 32 + np * 16 + b_row) * PITCH + kb + b_kb);
                ldsm_x4(bhi[np], sBh + boff);
                ldsm_x4(blo[np], sBl + boff);
            }
            uint32_t ahi[4][4], alo[4][4];
#pragma unroll
            for (int mi = 0; mi < 4; mi++) {
                uint32_t aoff = (uint32_t)((warp_m * 64 + mi * 16 + a_row) * PITCH + kb + a_kb);
                ldsm_x4(ahi[mi], sAh + aoff);
                ldsm_x4(alo[mi], sAl + aoff);
            }
#pragma unroll
            for (int mi = 0; mi < 4; mi++) {
                mma16816(acc[mi][0], ahi[mi], bhi[0][0], bhi[0][1]);
                mma16816(acc[mi][1], ahi[mi], bhi[0][2], bhi[0][3]);
                mma16816(acc[mi][2], ahi[mi], bhi[1][0], bhi[1][1]);
                mma16816(acc[mi][3], ahi[mi], bhi[1][2], bhi[1][3]);
            }
#pragma unroll
            for (int mi = 0; mi < 4; mi++) {
                mma16816(acc[mi][0], ahi[mi], blo[0][0], blo[0][1]);
                mma16816(acc[mi][1], ahi[mi], blo[0][2], blo[0][3]);
                mma16816(acc[mi][2], ahi[mi], blo[1][0], blo[1][1]);
                mma16816(acc[mi][3], ahi[mi], blo[1][2], blo[1][3]);
            }
#pragma unroll
            for (int mi = 0; mi < 4; mi++) {
                mma16816(acc[mi][0], alo[mi], bhi[0][0], bhi[0][1]);
                mma16816(acc[mi][1], alo[mi], bhi[0][2], bhi[0][3]);
                mma16816(acc[mi][2], alo[mi], bhi[1][0], bhi[1][1]);
                mma16816(acc[mi][3], alo[mi], bhi[1][2], bhi[1][3]);
            }
        }
        s ^= 1;
    }

    const int row0 = blockIdx.y * 128 + warp_m * 64;
    const int col0 = blockIdx.x * 128 + warp_n * 32;

    if (EPI == 1) {
#pragma unroll
        for (int mi = 0; mi < 4; mi++) {
#pragma unroll
            for (int ni = 0; ni < 4; ni++) {
                int col = col0 + ni * 8 + (lane & 3) * 2;
                float bx0 = bias[col], bx1 = bias[col + 1];
                int r0 = row0 + mi * 16 + (lane >> 2);
                float2 v0 = make_float2(acc[mi][ni][0] + bx0, acc[mi][ni][1] + bx1);
                float2 v1 = make_float2(acc[mi][ni][2] + bx0, acc[mi][ni][3] + bx1);
                *(float2*)(out + (size_t)r0 * 256 + col)       = v0;
                *(float2*)(out + (size_t)(r0 + 8) * 256 + col) = v1;
            }
        }
    } else {
#pragma unroll
        for (int mi = 0; mi < 4; mi++) {
#pragma unroll
            for (int ni = 0; ni < 4; ni++) {
#pragma unroll
                for (int id = 0; id < 4; id++) {
                    int row = row0 + mi * 16 + (lane >> 2) + 8 * (id >> 1);
                    int col = col0 + ni * 8 + (lane & 3) * 2 + (id & 1);
                    float v = acc[mi][ni][id] + bias[col];
                    int s2 = col % 3;
                    int hd = col / 3;
                    int h = hd >> 5, d = hd & 31;
                    int b = row / 49, n = row - b * 49;
                    size_t addr = (size_t)(b * NH + h) * (NTOK * HD) + n * HD + d;
                    if (s2 == 0)      g_Q[addr] = v * QSCALE;
                    else if (s2 == 1) g_K[addr] = v;
                    else              g_V[addr] = v;
                }
            }
        }
    }
}

// ======================= attention v2 =======================================
// One CTA per (window, head). 256 threads, warp-per-query-row fused softmax.
#define KPITCH 36
#define PPITCH 52
__global__ __launch_bounds__(256)
void attn_kernel(const int* __restrict__ mask, const float* __restrict__ bias_table)
{
    __shared__ float sQ[NTOK * HD];
    __shared__ float sK[NTOK * KPITCH];
    __shared__ float sV[NTOK * HD];
    __shared__ float sP[NTOK * PPITCH];
    __shared__ float sBias[169];

    const int bh = blockIdx.x;
    const int b = bh >> 3, h = bh & 7;
    const int tid = threadIdx.x;
    const int warp = tid >> 5, lane = tid & 31;

    const float4* Qb = (const float4*)(g_Q + (size_t)bh * NTOK * HD);
    const float4* Kb = (const float4*)(g_K + (size_t)bh * NTOK * HD);
    const float4* Vb = (const float4*)(g_V + (size_t)bh * NTOK * HD);

    for (int i = tid; i < NTOK * 8; i += 256) {   // 392 float4
        ((float4*)sQ)[i] = Qb[i];
        ((float4*)sV)[i] = Vb[i];
        float4 kv = Kb[i];
        int r = i >> 3, c = (i & 7) << 2;
        *(float4*)(sK + r * KPITCH + c) = kv;
    }
    if (tid < 169) sBias[tid] = bias_table[tid * NH + h];
    __syncthreads();

    // per-lane k decomposition (constant over rows)
    const int k0 = lane, k1 = lane + 32;
    const bool v1 = (k1 < NTOK);
    const int ki0 = k0 / 7, kj0 = k0 - ki0 * 7;
    const int ki1 = k1 / 7, kj1 = k1 - ki1 * 7;
    const float* kr0 = sK + k0 * KPITCH;
    const float* kr1 = sK + (v1 ? k1 : k0) * KPITCH;

    for (int q = warp; q < NTOK; q += 8) {
        float s0 = 0.f, s1 = 0.f;
        const float* qrow = sQ + q * HD;
#pragma unroll
        for (int d4 = 0; d4 < 8; d4++) {
            float4 qv = *(const float4*)(qrow + d4 * 4);      // broadcast
            float4 a0 = *(const float4*)(kr0 + d4 * 4);
            float4 a1 = *(const float4*)(kr1 + d4 * 4);
            s0 = fmaf(qv.x, a0.x, s0); s1 = fmaf(qv.x, a1.x, s1);
            s0 = fmaf(qv.y, a0.y, s0); s1 = fmaf(qv.y, a1.y, s1);
            s0 = fmaf(qv.z, a0.z, s0); s1 = fmaf(qv.z, a1.z, s1);
            s0 = fmaf(qv.w, a0.w, s0); s1 = fmaf(qv.w, a1.w, s1);
        }
        const int qi = q / 7, qj = q - qi * 7;
        const int* mrow = mask + (size_t)b * (NTOK * NTOK) + q * NTOK;
        int m0 = mrow[k0];
        int m1 = v1 ? mrow[k1] : 0;
        s0 += sBias[(qi - ki0 + 6) * 13 + (qj - kj0 + 6)] + (1.0f - (float)m0) * (-1e10f);
        if (v1) s1 += sBias[(qi - ki1 + 6) * 13 + (qj - kj1 + 6)] + (1.0f - (float)m1) * (-1e10f);
        else    s1 = -3.0e38f;

        // warp softmax over 49 values (2 per lane)
        float mx = fmaxf(s0, s1);
#pragma unroll
        for (int off = 16; off; off >>= 1)
            mx = fmaxf(mx, __shfl_xor_sync(0xffffffffu, mx, off));
        float e0 = __expf(s0 - mx);
        float e1 = v1 ? __expf(s1 - mx) : 0.f;
        float sum = e0 + e1;
#pragma unroll
        for (int off = 16; off; off >>= 1)
            sum += __shfl_xor_sync(0xffffffffu, sum, off);
        float inv = 1.0f / sum;
        sP[q * PPITCH + k0] = e0 * inv;
        if (v1) sP[q * PPITCH + k1] = e1 * inv;
    }
    __syncthreads();

    // O = P V -> chi/clo
    __nv_bfloat16* chiw = g_chi + ((size_t)b * NTOK) * DIMV + h * HD;
    __nv_bfloat16* clow = g_clo + ((size_t)b * NTOK) * DIMV + h * HD;
#pragma unroll 1
    for (int e = tid; e < NTOK * HD; e += 256) {
        int qq = e >> 5, d = e & 31;
        const float* pr = sP + qq * PPITCH;
        float s0 = 0.f, s1 = 0.f;
#pragma unroll
        for (int k = 0; k < 48; k += 2) {
            s0 = fmaf(pr[k],     sV[k * HD + d],       s0);
            s1 = fmaf(pr[k + 1], sV[(k + 1) * HD + d], s1);
        }
        float s = s0 + s1 + pr[48] * sV[48 * HD + d];
        __nv_bfloat16 hv = __float2bfloat16(s);
        chiw[(size_t)qq * DIMV + d] = hv;
        clow[(size_t)qq * DIMV + d] = __float2bfloat16(s - __bfloat162float(hv));
    }
}

// ============================================================================
extern "C" void kernel_launch(void* const* d_in, const int* in_sizes, int n_in,
                              void* d_out, int out_size)
{
    const float* x       = (const float*)d_in[0];
    const int*   mask    = (const int*)d_in[1];
    const float* qkv_w   = (const float*)d_in[2];
    const float* qkv_b   = (const float*)d_in[3];
    const float* proj_w  = (const float*)d_in[4];
    const float* proj_b  = (const float*)d_in[5];
    const float* rel_tbl = (const float*)d_in[6];
    float* out = (float*)d_out;

    __nv_bfloat16 *xhi, *xlo, *wqh, *wql, *wph, *wpl;
    cudaGetSymbolAddress((void**)&xhi, g_xhi);
    cudaGetSymbolAddress((void**)&xlo, g_xlo);
    cudaGetSymbolAddress((void**)&wqh, g_wqh);
    cudaGetSymbolAddress((void**)&wql, g_wql);
    cudaGetSymbolAddress((void**)&wph, g_wph);
    cudaGetSymbolAddress((void**)&wpl, g_wpl);

    constexpr int SMEMB = 2 * 4 * 128 * 80;    // 81920
    cudaFuncSetAttribute(mma_gemm<0>, cudaFuncAttributeMaxDynamicSharedMemorySize, SMEMB);
    cudaFuncSetAttribute(mma_gemm<1>, cudaFuncAttributeMaxDynamicSharedMemorySize, SMEMB);

    k_split_x<<<MTOT * 256 / 1024, 256>>>(x, xhi, xlo);
    k_split_w<<<768, 256>>>(qkv_w, wqh, wql, 768);
    k_split_w<<<256, 256>>>(proj_w, wph, wpl, 256);

    mma_gemm<0><<<dim3(6, MTOT / 128), 256, SMEMB>>>(qkv_b, nullptr);

    attn_kernel<<<BWIN * NH, 256>>>(mask, rel_tbl);

    mma_gemm<1><<<dim3(2, MTOT / 128), 256, SMEMB>>>(proj_b, out);
}